// round 15
// baseline (speedup 1.0000x reference)
#include <cuda_runtime.h>

// SuperpositionNeuron: out[r] = should_measure ? interfered[argmax(interfered+gumbel)]
//                                              : mean(interfered)
// interfered = sigmoid(x@W + b) @ M^T ;  B = 1048576, D = 128, S = 4.
//
// R10: R9 skeleton with (a) ONE barrier per stage instead of two (write target
// buf[(s+1)&1]'s readers were stage s-1, already fenced by its end-of-stage
// barrier), and (b) 128-thread blocks -> smaller sync domains, 8 independent
// CTAs/SM at the same 32 warps/SM. Swizzle: element j of row r at slot
// j ^ ((r>>1)&3); conflict-free on both STS.128 and LDS.128 phases.

#define D_DIM     128
#define TILE_ROWS 128
#define SUB_F4    4        // float4 per row per sub-tile (16 cols)

__constant__ float cW[512];   // [128][4] row-major
__constant__ float cM[16];    // [4][4]
__constant__ float cb[4];
__constant__ float cthr[1];

__global__ void __launch_bounds__(128, 8) sn_kernel(
    const float4* __restrict__ x4,      // [B, 32] float4 view of x[B,128]
    const float*  __restrict__ noise,   // [B]
    const float*  __restrict__ u,       // [B]
    const float4* __restrict__ gumbel4, // [B] float4 view of gumbel[B,4]
    float* __restrict__ out)            // [B]
{
    __shared__ float4 buf[2][TILE_ROWS * SUB_F4];   // 2 x 8 KB

    const int tid = threadIdx.x;
    const int tb  = blockIdx.x * TILE_ROWS;
    const int row = tb + tid;

    const int rx = (tid >> 1) & 3;   // XOR-swizzle key for this thread's row

    // ---- prologue: coop-load sub-tile 0 (cols 0..15) ----
    // f = i*128 + tid ; r = f>>2 ; j = f&3
    float4 p[4];
#pragma unroll
    for (int i = 0; i < 4; i++) {
        int f = i * 128 + tid, r = f >> 2, j = f & 3;
        p[i] = __ldcs(x4 + (size_t)(tb + r) * 32 + j);
    }

    // epilogue inputs: coalesced, issued behind the critical x stream
    float  nz = __ldg(noise + row);
    float  uu = __ldg(u + row);
    float4 g  = __ldg(gumbel4 + row);

#pragma unroll
    for (int i = 0; i < 4; i++) {
        int f = i * 128 + tid, r = f >> 2, j = f & 3;
        buf[0][r * 4 + (j ^ ((r >> 1) & 3))] = p[i];
    }
    __syncthreads();

    float acc0 = 0.f, acc1 = 0.f, acc2 = 0.f, acc3 = 0.f;

#pragma unroll
    for (int s = 0; s < 8; s++) {
        // prefetch next sub-tile into registers (overlaps compute below)
        if (s < 7) {
#pragma unroll
            for (int i = 0; i < 4; i++) {
                int f = i * 128 + tid, r = f >> 2, j = f & 3;
                p[i] = __ldcs(x4 + (size_t)(tb + r) * 32 + (s + 1) * 4 + j);
            }
        }

        // ---- compute: this thread's row, cols s*16 .. s*16+15 ----
        // Slot (cc^rx) holds element cc of this row; W indexed by cc
        // (compile-time uniform -> constant-bank loads).
#pragma unroll
        for (int cc = 0; cc < 4; cc++) {
            float4 xv = buf[s & 1][tid * 4 + (cc ^ rx)];
            const float* w = &cW[(s * 4 + cc) * 16];  // W rows 4*(s*4+cc)..+3
            acc0 += xv.x * w[0] + xv.y * w[4] + xv.z * w[8]  + xv.w * w[12];
            acc1 += xv.x * w[1] + xv.y * w[5] + xv.z * w[9]  + xv.w * w[13];
            acc2 += xv.x * w[2] + xv.y * w[6] + xv.z * w[10] + xv.w * w[14];
            acc3 += xv.x * w[3] + xv.y * w[7] + xv.z * w[11] + xv.w * w[15];
        }

        // stage next sub-tile; single barrier is sufficient: readers of
        // buf[(s+1)&1] were stage s-1, fenced by its end-of-stage barrier.
        if (s < 7) {
#pragma unroll
            for (int i = 0; i < 4; i++) {
                int f = i * 128 + tid, r = f >> 2, j = f & 3;
                buf[(s + 1) & 1][r * 4 + (j ^ ((r >> 1) & 3))] = p[i];
            }
            __syncthreads();
        }
    }

    // ---- dense epilogue (every lane = one row) ----
    float s0 = 1.f / (1.f + __expf(-(acc0 + cb[0])));
    float s1 = 1.f / (1.f + __expf(-(acc1 + cb[1])));
    float s2 = 1.f / (1.f + __expf(-(acc2 + cb[2])));
    float s3 = 1.f / (1.f + __expf(-(acc3 + cb[3])));

    float i0 = cM[0]  * s0 + cM[1]  * s1 + cM[2]  * s2 + cM[3]  * s3;
    float i1 = cM[4]  * s0 + cM[5]  * s1 + cM[6]  * s2 + cM[7]  * s3;
    float i2 = cM[8]  * s0 + cM[9]  * s1 + cM[10] * s2 + cM[11] * s3;
    float i3 = cM[12] * s0 + cM[13] * s1 + cM[14] * s2 + cM[15] * s3;

    float mp = 1.f / (1.f + __expf(-(nz + cthr[0])));
    bool should_measure = uu < mp;

    // gumbel-argmax (first-max tiebreak, matching jnp.argmax)
    float v0 = i0 + g.x, v1 = i1 + g.y, v2 = i2 + g.z, v3 = i3 + g.w;
    float best = v0, mv = i0;
    if (v1 > best) { best = v1; mv = i1; }
    if (v2 > best) { best = v2; mv = i2; }
    if (v3 > best) { best = v3; mv = i3; }

    float mean = 0.25f * (i0 + i1 + i2 + i3);
    __stcs(out + row, should_measure ? mv : mean);
}

extern "C" void kernel_launch(void* const* d_in, const int* in_sizes, int n_in,
                              void* d_out, int out_size)
{
    const float* x      = (const float*)d_in[0];
    const float* W      = (const float*)d_in[1];
    const float* b      = (const float*)d_in[2];
    const float* M      = (const float*)d_in[3];
    const float* thr    = (const float*)d_in[4];
    const float* noise  = (const float*)d_in[5];
    const float* u      = (const float*)d_in[6];
    const float* gumbel = (const float*)d_in[7];
    float* out = (float*)d_out;

    // small uniform params -> constant bank (D2D async copies, capturable)
    cudaMemcpyToSymbolAsync(cW,   W,   512 * sizeof(float), 0, cudaMemcpyDeviceToDevice, 0);
    cudaMemcpyToSymbolAsync(cM,   M,    16 * sizeof(float), 0, cudaMemcpyDeviceToDevice, 0);
    cudaMemcpyToSymbolAsync(cb,   b,     4 * sizeof(float), 0, cudaMemcpyDeviceToDevice, 0);
    cudaMemcpyToSymbolAsync(cthr, thr,       sizeof(float), 0, cudaMemcpyDeviceToDevice, 0);

    int B = in_sizes[0] / D_DIM;              // 1048576
    int blocks = B / TILE_ROWS;               // 8192
    sn_kernel<<<blocks, TILE_ROWS>>>((const float4*)x, noise, u,
                                     (const float4*)gumbel, out);
}

// round 16
// speedup vs baseline: 1.0064x; 1.0064x over previous
#include <cuda_runtime.h>

// SuperpositionNeuron: out[r] = should_measure ? interfered[argmax(interfered+gumbel)]
//                                              : mean(interfered)
// interfered = sigmoid(x@W + b) @ M^T ;  B = 1048576, D = 128, S = 4.
//
// R10: R9 skeleton with (a) ONE barrier per stage instead of two (write target
// buf[(s+1)&1]'s readers were stage s-1, already fenced by its end-of-stage
// barrier), and (b) 128-thread blocks -> smaller sync domains, 8 independent
// CTAs/SM at the same 32 warps/SM. Swizzle: element j of row r at slot
// j ^ ((r>>1)&3); conflict-free on both STS.128 and LDS.128 phases.

#define D_DIM     128
#define TILE_ROWS 128
#define SUB_F4    4        // float4 per row per sub-tile (16 cols)

__constant__ float cW[512];   // [128][4] row-major
__constant__ float cM[16];    // [4][4]
__constant__ float cb[4];
__constant__ float cthr[1];

__global__ void __launch_bounds__(128, 8) sn_kernel(
    const float4* __restrict__ x4,      // [B, 32] float4 view of x[B,128]
    const float*  __restrict__ noise,   // [B]
    const float*  __restrict__ u,       // [B]
    const float4* __restrict__ gumbel4, // [B] float4 view of gumbel[B,4]
    float* __restrict__ out)            // [B]
{
    __shared__ float4 buf[2][TILE_ROWS * SUB_F4];   // 2 x 8 KB

    const int tid = threadIdx.x;
    const int tb  = blockIdx.x * TILE_ROWS;
    const int row = tb + tid;

    const int rx = (tid >> 1) & 3;   // XOR-swizzle key for this thread's row

    // ---- prologue: coop-load sub-tile 0 (cols 0..15) ----
    // f = i*128 + tid ; r = f>>2 ; j = f&3
    float4 p[4];
#pragma unroll
    for (int i = 0; i < 4; i++) {
        int f = i * 128 + tid, r = f >> 2, j = f & 3;
        p[i] = __ldcs(x4 + (size_t)(tb + r) * 32 + j);
    }

    // epilogue inputs: coalesced, issued behind the critical x stream
    float  nz = __ldg(noise + row);
    float  uu = __ldg(u + row);
    float4 g  = __ldg(gumbel4 + row);

#pragma unroll
    for (int i = 0; i < 4; i++) {
        int f = i * 128 + tid, r = f >> 2, j = f & 3;
        buf[0][r * 4 + (j ^ ((r >> 1) & 3))] = p[i];
    }
    __syncthreads();

    float acc0 = 0.f, acc1 = 0.f, acc2 = 0.f, acc3 = 0.f;

#pragma unroll
    for (int s = 0; s < 8; s++) {
        // prefetch next sub-tile into registers (overlaps compute below)
        if (s < 7) {
#pragma unroll
            for (int i = 0; i < 4; i++) {
                int f = i * 128 + tid, r = f >> 2, j = f & 3;
                p[i] = __ldcs(x4 + (size_t)(tb + r) * 32 + (s + 1) * 4 + j);
            }
        }

        // ---- compute: this thread's row, cols s*16 .. s*16+15 ----
        // Slot (cc^rx) holds element cc of this row; W indexed by cc
        // (compile-time uniform -> constant-bank loads).
#pragma unroll
        for (int cc = 0; cc < 4; cc++) {
            float4 xv = buf[s & 1][tid * 4 + (cc ^ rx)];
            const float* w = &cW[(s * 4 + cc) * 16];  // W rows 4*(s*4+cc)..+3
            acc0 += xv.x * w[0] + xv.y * w[4] + xv.z * w[8]  + xv.w * w[12];
            acc1 += xv.x * w[1] + xv.y * w[5] + xv.z * w[9]  + xv.w * w[13];
            acc2 += xv.x * w[2] + xv.y * w[6] + xv.z * w[10] + xv.w * w[14];
            acc3 += xv.x * w[3] + xv.y * w[7] + xv.z * w[11] + xv.w * w[15];
        }

        // stage next sub-tile; single barrier is sufficient: readers of
        // buf[(s+1)&1] were stage s-1, fenced by its end-of-stage barrier.
        if (s < 7) {
#pragma unroll
            for (int i = 0; i < 4; i++) {
                int f = i * 128 + tid, r = f >> 2, j = f & 3;
                buf[(s + 1) & 1][r * 4 + (j ^ ((r >> 1) & 3))] = p[i];
            }
            __syncthreads();
        }
    }

    // ---- dense epilogue (every lane = one row) ----
    float s0 = 1.f / (1.f + __expf(-(acc0 + cb[0])));
    float s1 = 1.f / (1.f + __expf(-(acc1 + cb[1])));
    float s2 = 1.f / (1.f + __expf(-(acc2 + cb[2])));
    float s3 = 1.f / (1.f + __expf(-(acc3 + cb[3])));

    float i0 = cM[0]  * s0 + cM[1]  * s1 + cM[2]  * s2 + cM[3]  * s3;
    float i1 = cM[4]  * s0 + cM[5]  * s1 + cM[6]  * s2 + cM[7]  * s3;
    float i2 = cM[8]  * s0 + cM[9]  * s1 + cM[10] * s2 + cM[11] * s3;
    float i3 = cM[12] * s0 + cM[13] * s1 + cM[14] * s2 + cM[15] * s3;

    float mp = 1.f / (1.f + __expf(-(nz + cthr[0])));
    bool should_measure = uu < mp;

    // gumbel-argmax (first-max tiebreak, matching jnp.argmax)
    float v0 = i0 + g.x, v1 = i1 + g.y, v2 = i2 + g.z, v3 = i3 + g.w;
    float best = v0, mv = i0;
    if (v1 > best) { best = v1; mv = i1; }
    if (v2 > best) { best = v2; mv = i2; }
    if (v3 > best) { best = v3; mv = i3; }

    float mean = 0.25f * (i0 + i1 + i2 + i3);
    __stcs(out + row, should_measure ? mv : mean);
}

extern "C" void kernel_launch(void* const* d_in, const int* in_sizes, int n_in,
                              void* d_out, int out_size)
{
    const float* x      = (const float*)d_in[0];
    const float* W      = (const float*)d_in[1];
    const float* b      = (const float*)d_in[2];
    const float* M      = (const float*)d_in[3];
    const float* thr    = (const float*)d_in[4];
    const float* noise  = (const float*)d_in[5];
    const float* u      = (const float*)d_in[6];
    const float* gumbel = (const float*)d_in[7];
    float* out = (float*)d_out;

    // small uniform params -> constant bank (D2D async copies, capturable)
    cudaMemcpyToSymbolAsync(cW,   W,   512 * sizeof(float), 0, cudaMemcpyDeviceToDevice, 0);
    cudaMemcpyToSymbolAsync(cM,   M,    16 * sizeof(float), 0, cudaMemcpyDeviceToDevice, 0);
    cudaMemcpyToSymbolAsync(cb,   b,     4 * sizeof(float), 0, cudaMemcpyDeviceToDevice, 0);
    cudaMemcpyToSymbolAsync(cthr, thr,       sizeof(float), 0, cudaMemcpyDeviceToDevice, 0);

    int B = in_sizes[0] / D_DIM;              // 1048576
    int blocks = B / TILE_ROWS;               // 8192
    sn_kernel<<<blocks, TILE_ROWS>>>((const float4*)x, noise, u,
                                     (const float4*)gumbel, out);
}